// round 3
// baseline (speedup 1.0000x reference)
#include <cuda_runtime.h>

#define NB     8
#define S_ENC  256
#define S_DEC  128
#define DIM    512     // D_ENC = D_DEC = UNITS = 512

// Scratch for projected encodings/decodings (no cudaMalloc allowed)
__device__ float g_denc[NB * S_ENC * DIM];   // [B, S_ENC, U]  4 MB
__device__ float g_ddec[NB * S_DEC * DIM];   // [B, S_DEC, U]  2 MB

// ---------------------------------------------------------------------------
// GEMM: C[M, 512] = X[M, 512] @ W[512, 512] + bias   (row-major everywhere)
// 64x64 block tile, BK=16, 256 threads, 4x4 per thread.
// ---------------------------------------------------------------------------
#define GBM 64
#define GBN 64
#define GBK 16

__global__ __launch_bounds__(256) void gemm_bias_kernel(
    const float* __restrict__ X,
    const float* __restrict__ W,
    const float* __restrict__ bias,
    float* __restrict__ C)
{
    __shared__ float As[GBK][GBM];   // transposed A tile
    __shared__ float Bs[GBK][GBN];

    const int tid = threadIdx.x;
    const int tx = tid & 15;         // 0..15  -> column group
    const int ty = tid >> 4;         // 0..15  -> row group
    const int row0 = blockIdx.y * GBM;
    const int col0 = blockIdx.x * GBN;

    // A-tile load mapping: 64 rows x 4 float4 (k)
    const int arow = tid >> 2;            // 0..63
    const int acol = (tid & 3) * 4;       // 0,4,8,12
    // B-tile load mapping: 16 rows x 16 float4 (n)
    const int brow = tid >> 4;            // 0..15
    const int bcol = (tid & 15) * 4;      // 0..60

    float acc[4][4] = {};

    for (int k0 = 0; k0 < DIM; k0 += GBK) {
        float4 a = *(const float4*)&X[(row0 + arow) * DIM + k0 + acol];
        float4 b = *(const float4*)&W[(k0 + brow) * DIM + col0 + bcol];
        As[acol + 0][arow] = a.x;
        As[acol + 1][arow] = a.y;
        As[acol + 2][arow] = a.z;
        As[acol + 3][arow] = a.w;
        *(float4*)&Bs[brow][bcol] = b;
        __syncthreads();

        #pragma unroll
        for (int k = 0; k < GBK; k++) {
            float4 av = *(const float4*)&As[k][ty * 4];
            float4 bv = *(const float4*)&Bs[k][tx * 4];
            float ar[4] = {av.x, av.y, av.z, av.w};
            float br[4] = {bv.x, bv.y, bv.z, bv.w};
            #pragma unroll
            for (int i = 0; i < 4; i++)
                #pragma unroll
                for (int j = 0; j < 4; j++)
                    acc[i][j] = fmaf(ar[i], br[j], acc[i][j]);
        }
        __syncthreads();
    }

    #pragma unroll
    for (int i = 0; i < 4; i++) {
        const int r = row0 + ty * 4 + i;
        #pragma unroll
        for (int j = 0; j < 4; j++) {
            const int c = col0 + tx * 4 + j;
            C[r * DIM + c] = acc[i][j] + bias[c];
        }
    }
}

// ---------------------------------------------------------------------------
// Attention kernel: one block = (batch b, tile of QT=8 decoder positions).
// Warp w owns q = w.  Scores -> softmax -> weighted context.
// ---------------------------------------------------------------------------
#define QT   8      // decoder positions per block (== number of warps)
#define EC   8      // encoder rows per SMEM chunk
#define ATH  256    // threads

__device__ __forceinline__ float tanh_approx(float x) {
    float y;
    asm("tanh.approx.f32 %0, %1;" : "=f"(y) : "f"(x));
    return y;
}

__global__ __launch_bounds__(ATH) void attn_kernel(
    const float* __restrict__ enc,      // [B, S_ENC, DIM] raw encodings
    const float* __restrict__ wscore,   // [DIM]
    const float* __restrict__ bscore,   // [1]
    float* __restrict__ out)            // [B, S_DEC, DIM]
{
    __shared__ float s_dd[QT * DIM];        // 16 KB  d_dec rows for this q-tile
    __shared__ float s_ws[DIM];             //  2 KB
    __shared__ float s_de[EC * DIM];        // 16 KB  d_enc chunk
    __shared__ float s_sc[QT][S_ENC];       //  8 KB  scores -> weights

    const int b    = blockIdx.y;
    const int q0   = blockIdx.x * QT;
    const int tid  = threadIdx.x;
    const int lane = tid & 31;
    const int w    = tid >> 5;      // warp id == local q

    // ---- stage shared operands --------------------------------------------
    for (int i = tid; i < DIM; i += ATH) s_ws[i] = wscore[i];
    {
        const float4* src = (const float4*)(g_ddec + (b * S_DEC + q0) * DIM);
        float4* dst = (float4*)s_dd;
        for (int i = tid; i < QT * DIM / 4; i += ATH) dst[i] = src[i];
    }
    __syncthreads();

    // per-lane registers: d_dec slice for q=w and W_score slice (lane-strided)
    float ddr[16], wsr[16];
    #pragma unroll
    for (int i = 0; i < 16; i++) {
        const int u = lane + 32 * i;
        ddr[i] = s_dd[w * DIM + u];
        wsr[i] = s_ws[u];
    }

    const float bsc = bscore[0];
    const float* dep = g_denc + b * S_ENC * DIM;

    // ---- scores ------------------------------------------------------------
    for (int ch = 0; ch < S_ENC / EC; ch++) {
        __syncthreads();   // previous chunk fully consumed
        {
            const float4* src = (const float4*)(dep + ch * EC * DIM);
            float4* dst = (float4*)s_de;
            for (int i = tid; i < EC * DIM / 4; i += ATH) dst[i] = src[i];
        }
        __syncthreads();

        #pragma unroll 2
        for (int e = 0; e < EC; e++) {
            float s = 0.f;
            #pragma unroll
            for (int i = 0; i < 16; i++) {
                const float x = ddr[i] + s_de[e * DIM + lane + 32 * i];
                s = fmaf(tanh_approx(x), wsr[i], s);
            }
            #pragma unroll
            for (int off = 16; off; off >>= 1)
                s += __shfl_xor_sync(0xFFFFFFFFu, s, off);
            if (lane == 0) s_sc[w][ch * EC + e] = s + bsc;
        }
    }
    __syncwarp();

    // ---- softmax over encoder positions (warp w handles q=w) --------------
    float v[S_ENC / 32];
    float m = -1e30f;
    #pragma unroll
    for (int i = 0; i < S_ENC / 32; i++) {
        v[i] = s_sc[w][lane + 32 * i];
        m = fmaxf(m, v[i]);
    }
    #pragma unroll
    for (int off = 16; off; off >>= 1)
        m = fmaxf(m, __shfl_xor_sync(0xFFFFFFFFu, m, off));
    float sum = 0.f;
    #pragma unroll
    for (int i = 0; i < S_ENC / 32; i++) {
        v[i] = __expf(v[i] - m);
        sum += v[i];
    }
    #pragma unroll
    for (int off = 16; off; off >>= 1)
        sum += __shfl_xor_sync(0xFFFFFFFFu, sum, off);
    const float inv = 1.f / sum;
    #pragma unroll
    for (int i = 0; i < S_ENC / 32; i++)
        s_sc[w][lane + 32 * i] = v[i] * inv;
    __syncthreads();

    // ---- context: warp w owns dims [w*64, w*64+64) across ALL q -----------
    const int d0 = w * 64 + lane;
    float acc0[QT] = {}, acc1[QT] = {};
    const float* ep = enc + b * S_ENC * DIM;

    #pragma unroll 4
    for (int e = 0; e < S_ENC; e++) {
        const float e0 = ep[e * DIM + d0];
        const float e1 = ep[e * DIM + d0 + 32];
        #pragma unroll
        for (int q = 0; q < QT; q++) {
            const float wq = s_sc[q][e];   // broadcast
            acc0[q] = fmaf(wq, e0, acc0[q]);
            acc1[q] = fmaf(wq, e1, acc1[q]);
        }
    }

    #pragma unroll
    for (int q = 0; q < QT; q++) {
        float* op = out + (b * S_DEC + q0 + q) * DIM;
        op[d0]      = acc0[q];
        op[d0 + 32] = acc1[q];
    }
}

// ---------------------------------------------------------------------------
extern "C" void kernel_launch(void* const* d_in, const int* in_sizes, int n_in,
                              void* d_out, int out_size)
{
    const float* encodings = (const float*)d_in[0];   // [8,256,512]
    const float* decodings = (const float*)d_in[1];   // [8,128,512]
    const float* W_enc     = (const float*)d_in[2];   // [512,512]
    const float* W_dec     = (const float*)d_in[3];   // [512,512]
    const float* W_score   = (const float*)d_in[4];   // [512,1]
    const float* bias_enc  = (const float*)d_in[5];   // [512]
    const float* bias_dec  = (const float*)d_in[6];   // [512]
    const float* bias_sc   = (const float*)d_in[7];   // [1]
    float* out = (float*)d_out;                       // [8,128,512]

    void* p_denc = nullptr;
    void* p_ddec = nullptr;
    cudaGetSymbolAddress(&p_denc, g_denc);
    cudaGetSymbolAddress(&p_ddec, g_ddec);

    // projections
    {
        dim3 grid(DIM / GBN, (NB * S_ENC) / GBM);   // (8, 32)
        gemm_bias_kernel<<<grid, 256>>>(encodings, W_enc, bias_enc, (float*)p_denc);
    }
    {
        dim3 grid(DIM / GBN, (NB * S_DEC) / GBM);   // (8, 16)
        gemm_bias_kernel<<<grid, 256>>>(decodings, W_dec, bias_dec, (float*)p_ddec);
    }

    // scores + softmax + context
    {
        dim3 grid(S_DEC / QT, NB);                  // (16, 8)
        attn_kernel<<<grid, ATH>>>(encodings, W_score, bias_sc, out);
    }
}

// round 4
// speedup vs baseline: 1.5696x; 1.5696x over previous
#include <cuda_runtime.h>

#define NB     8
#define S_ENC  256
#define S_DEC  128
#define DIM    512     // D_ENC = D_DEC = UNITS = 512

// Scratch for projected encodings/decodings (no cudaMalloc allowed)
__device__ float g_denc[NB * S_ENC * DIM];   // [B, S_ENC, U]
__device__ float g_ddec[NB * S_DEC * DIM];   // [B, S_DEC, U]

// ---------------------------------------------------------------------------
// Merged GEMM: z=0 -> d_enc = enc @ W_enc + b_enc  (M=2048)
//              z=1 -> d_dec = dec @ W_dec + b_dec  (M=1024)
// 64x64 tile, BK=16, 256 threads, 4x4/thread, register-prefetched loads.
// ---------------------------------------------------------------------------
#define GBM 64
#define GBN 64
#define GBK 16

__global__ __launch_bounds__(256) void gemm_bias_kernel(
    const float* __restrict__ Xe, const float* __restrict__ We,
    const float* __restrict__ be, float* __restrict__ Ce,
    const float* __restrict__ Xd, const float* __restrict__ Wd,
    const float* __restrict__ bd, float* __restrict__ Cd)
{
    const int z = blockIdx.z;
    if (z == 1 && blockIdx.y >= (NB * S_DEC) / GBM) return;

    const float* __restrict__ X    = z ? Xd : Xe;
    const float* __restrict__ W    = z ? Wd : We;
    const float* __restrict__ bias = z ? bd : be;
    float* __restrict__ C          = z ? Cd : Ce;

    __shared__ float As[GBK][GBM];   // transposed A tile
    __shared__ float Bs[GBK][GBN];

    const int tid = threadIdx.x;
    const int tx = tid & 15;
    const int ty = tid >> 4;
    const int row0 = blockIdx.y * GBM;
    const int col0 = blockIdx.x * GBN;

    const int arow = tid >> 2;            // 0..63
    const int acol = (tid & 3) * 4;       // 0,4,8,12
    const int brow = tid >> 4;            // 0..15
    const int bcol = (tid & 15) * 4;      // 0..60

    float acc[4][4] = {};

    // prefetch first tile into registers
    float4 ra = *(const float4*)&X[(row0 + arow) * DIM + acol];
    float4 rb = *(const float4*)&W[brow * DIM + col0 + bcol];

    for (int k0 = 0; k0 < DIM; k0 += GBK) {
        As[acol + 0][arow] = ra.x;
        As[acol + 1][arow] = ra.y;
        As[acol + 2][arow] = ra.z;
        As[acol + 3][arow] = ra.w;
        *(float4*)&Bs[brow][bcol] = rb;
        __syncthreads();

        // issue next tile's loads; latency hidden behind the FMA block below
        if (k0 + GBK < DIM) {
            ra = *(const float4*)&X[(row0 + arow) * DIM + k0 + GBK + acol];
            rb = *(const float4*)&W[(k0 + GBK + brow) * DIM + col0 + bcol];
        }

        #pragma unroll
        for (int k = 0; k < GBK; k++) {
            float4 av = *(const float4*)&As[k][ty * 4];
            float4 bv = *(const float4*)&Bs[k][tx * 4];
            float ar[4] = {av.x, av.y, av.z, av.w};
            float br[4] = {bv.x, bv.y, bv.z, bv.w};
            #pragma unroll
            for (int i = 0; i < 4; i++)
                #pragma unroll
                for (int j = 0; j < 4; j++)
                    acc[i][j] = fmaf(ar[i], br[j], acc[i][j]);
        }
        __syncthreads();
    }

    #pragma unroll
    for (int i = 0; i < 4; i++) {
        const int r = row0 + ty * 4 + i;
        #pragma unroll
        for (int j = 0; j < 4; j++) {
            const int c = col0 + tx * 4 + j;
            C[r * DIM + c] = acc[i][j] + bias[c];
        }
    }
}

// ---------------------------------------------------------------------------
// Attention kernel: block = (batch b, tile of QT=8 q's). 8 warps, warp w -> q=w.
// Lane-owns-e score layout: lane l accumulates score[q][e] fully in a register
// (no per-e shuffle tree). d_enc streamed in EC=16-row chunks, double-buffered,
// XOR-swizzled for conflict-free strided float4 reads.
// ---------------------------------------------------------------------------
#define QT   8
#define EC   16
#define NCH  (S_ENC / EC)        // 16
#define ATH  256
#define CHV  (EC * DIM / 4)      // 2048 float4 per chunk
#define PFT  (CHV / ATH)         // 8 float4 per thread

__device__ __forceinline__ float tanh_approx(float x) {
    float y;
    asm("tanh.approx.f32 %0, %1;" : "=f"(y) : "f"(x));
    return y;
}

__global__ __launch_bounds__(ATH) void attn_kernel(
    const float* __restrict__ enc,      // [B, S_ENC, DIM] raw encodings
    const float* __restrict__ wscore,   // [DIM]
    const float* __restrict__ bscore,   // [1]
    float* __restrict__ out)            // [B, S_DEC, DIM]
{
    extern __shared__ float smem[];
    float* s_dd = smem;                      // QT*DIM      (4096 f)
    float* s_ws = s_dd + QT * DIM;           // DIM         (512 f)
    float* s_sc = s_ws + DIM;                // QT*S_ENC    (2048 f)
    float* s_de = s_sc + QT * S_ENC;         // 2*EC*DIM    (16384 f)

    const int b    = blockIdx.y;
    const int q0   = blockIdx.x * QT;
    const int tid  = threadIdx.x;
    const int lane = tid & 31;
    const int w    = tid >> 5;      // warp id == local q

    // ---- stage d_dec rows + w_score ---------------------------------------
    for (int i = tid; i < DIM; i += ATH) s_ws[i] = wscore[i];
    {
        const float4* src = (const float4*)(g_ddec + (b * S_DEC + q0) * DIM);
        float4* dst = (float4*)s_dd;
        for (int i = tid; i < QT * DIM / 4; i += ATH) dst[i] = src[i];
    }

    const float bsc = bscore[0];
    const float4* gsrc = (const float4*)(g_denc + b * S_ENC * DIM);
    float4* sde4 = (float4*)s_de;

    // prefetch chunk 0 -> regs, store, prefetch chunk 1 -> regs
    float4 r[PFT];
    #pragma unroll
    for (int j = 0; j < PFT; j++) r[j] = gsrc[j * ATH + tid];
    #pragma unroll
    for (int j = 0; j < PFT; j++) {
        const int i = j * ATH + tid;
        const int e = i >> 7, v = i & 127;
        sde4[(e << 7) | (v ^ (e & 7))] = r[j];
    }
    #pragma unroll
    for (int j = 0; j < PFT; j++) r[j] = gsrc[CHV + j * ATH + tid];
    __syncthreads();

    // per-warp compute setup
    const int e_loc = lane & 15;
    const int half  = lane >> 4;
    const int sw    = e_loc & 7;
    const float4* dd4 = (const float4*)s_dd + w * (DIM / 4);
    const float4* ws4 = (const float4*)s_ws;
    const int v0 = half * 64;

    // ---- score chunks ------------------------------------------------------
    for (int ch = 0; ch < NCH; ch++) {
        const float4* de4 = (const float4*)s_de + (ch & 1) * CHV + e_loc * (DIM / 4);
        float s0 = 0.f, s1 = 0.f;
        #pragma unroll 16
        for (int v = v0; v < v0 + 64; v++) {
            const float4 d  = dd4[v];
            const float4 wv = ws4[v];
            const float4 ev = de4[v ^ sw];
            s0 = fmaf(tanh_approx(d.x + ev.x), wv.x, s0);
            s1 = fmaf(tanh_approx(d.y + ev.y), wv.y, s1);
            s0 = fmaf(tanh_approx(d.z + ev.z), wv.z, s0);
            s1 = fmaf(tanh_approx(d.w + ev.w), wv.w, s1);
        }
        float tot = s0 + s1;
        tot += __shfl_xor_sync(0xFFFFFFFFu, tot, 16);
        if (lane < 16) s_sc[w * S_ENC + ch * EC + e_loc] = tot + bsc;

        __syncthreads();   // everyone done with buf[(ch+1)&1] (from chunk ch-1)
        if (ch + 1 < NCH) {
            float4* dbuf = sde4 + ((ch + 1) & 1) * CHV;
            #pragma unroll
            for (int j = 0; j < PFT; j++) {
                const int i = j * ATH + tid;
                const int e = i >> 7, v = i & 127;
                dbuf[(e << 7) | (v ^ (e & 7))] = r[j];
            }
            if (ch + 2 < NCH) {
                #pragma unroll
                for (int j = 0; j < PFT; j++)
                    r[j] = gsrc[(ch + 2) * CHV + j * ATH + tid];
            }
            __syncthreads();   // new buffer visible
        }
    }

    // ---- softmax over encoder positions (warp w handles q=w) --------------
    float v[S_ENC / 32];
    float m = -1e30f;
    #pragma unroll
    for (int i = 0; i < S_ENC / 32; i++) {
        v[i] = s_sc[w * S_ENC + lane + 32 * i];
        m = fmaxf(m, v[i]);
    }
    #pragma unroll
    for (int off = 16; off; off >>= 1)
        m = fmaxf(m, __shfl_xor_sync(0xFFFFFFFFu, m, off));
    float sum = 0.f;
    #pragma unroll
    for (int i = 0; i < S_ENC / 32; i++) {
        v[i] = __expf(v[i] - m);
        sum += v[i];
    }
    #pragma unroll
    for (int off = 16; off; off >>= 1)
        sum += __shfl_xor_sync(0xFFFFFFFFu, sum, off);
    const float inv = 1.f / sum;
    #pragma unroll
    for (int i = 0; i < S_ENC / 32; i++)
        s_sc[w * S_ENC + lane + 32 * i] = v[i] * inv;
    __syncthreads();

    // ---- context: warp w owns dims [w*64, w*64+64) across ALL q -----------
    const int d0 = w * 64 + lane;
    float acc0[QT] = {}, acc1[QT] = {};
    const float* ep = enc + b * S_ENC * DIM;

    #pragma unroll 4
    for (int e = 0; e < S_ENC; e++) {
        const float e0 = ep[e * DIM + d0];
        const float e1 = ep[e * DIM + d0 + 32];
        #pragma unroll
        for (int q = 0; q < QT; q++) {
            const float wq = s_sc[q * S_ENC + e];   // broadcast
            acc0[q] = fmaf(wq, e0, acc0[q]);
            acc1[q] = fmaf(wq, e1, acc1[q]);
        }
    }

    #pragma unroll
    for (int q = 0; q < QT; q++) {
        float* op = out + (b * S_DEC + q0 + q) * DIM;
        op[d0]      = acc0[q];
        op[d0 + 32] = acc1[q];
    }
}

#define ATTN_SMEM ((QT * DIM + DIM + QT * S_ENC + 2 * EC * DIM) * (int)sizeof(float))

// ---------------------------------------------------------------------------
extern "C" void kernel_launch(void* const* d_in, const int* in_sizes, int n_in,
                              void* d_out, int out_size)
{
    const float* encodings = (const float*)d_in[0];   // [8,256,512]
    const float* decodings = (const float*)d_in[1];   // [8,128,512]
    const float* W_enc     = (const float*)d_in[2];   // [512,512]
    const float* W_dec     = (const float*)d_in[3];   // [512,512]
    const float* W_score   = (const float*)d_in[4];   // [512,1]
    const float* bias_enc  = (const float*)d_in[5];   // [512]
    const float* bias_dec  = (const float*)d_in[6];   // [512]
    const float* bias_sc   = (const float*)d_in[7];   // [1]
    float* out = (float*)d_out;                       // [8,128,512]

    void* p_denc = nullptr;
    void* p_ddec = nullptr;
    cudaGetSymbolAddress(&p_denc, g_denc);
    cudaGetSymbolAddress(&p_ddec, g_ddec);

    cudaFuncSetAttribute(attn_kernel,
                         cudaFuncAttributeMaxDynamicSharedMemorySize, ATTN_SMEM);

    // both projections in one launch (z dimension selects)
    {
        dim3 grid(DIM / GBN, (NB * S_ENC) / GBM, 2);   // (8, 32, 2)
        gemm_bias_kernel<<<grid, 256>>>(encodings, W_enc, bias_enc, (float*)p_denc,
                                        decodings, W_dec, bias_dec, (float*)p_ddec);
    }

    // scores + softmax + context
    {
        dim3 grid(S_DEC / QT, NB);                     // (16, 8)
        attn_kernel<<<grid, ATH, ATTN_SMEM>>>(encodings, W_score, bias_sc, out);
    }
}

// round 6
// speedup vs baseline: 1.6472x; 1.0494x over previous
#include <cuda_runtime.h>

#define NB     8
#define S_ENC  256
#define S_DEC  128
#define DIM    512     // D_ENC = D_DEC = UNITS = 512

// Scratch for projected encodings/decodings (no cudaMalloc allowed)
__device__ float g_denc[NB * S_ENC * DIM];   // [B, S_ENC, U]
__device__ float g_ddec[NB * S_DEC * DIM];   // [B, S_DEC, U]

// ---------------------------------------------------------------------------
// Merged GEMM: z=0 -> d_enc = enc @ W_enc + b_enc  (M=2048)
//              z=1 -> d_dec = dec @ W_dec + b_dec  (M=1024)
// 64x64 tile, BK=16, 256 threads, 4x4/thread, register-prefetched loads.
// ---------------------------------------------------------------------------
#define GBM 64
#define GBN 64
#define GBK 16

__global__ __launch_bounds__(256) void gemm_bias_kernel(
    const float* __restrict__ Xe, const float* __restrict__ We,
    const float* __restrict__ be, float* __restrict__ Ce,
    const float* __restrict__ Xd, const float* __restrict__ Wd,
    const float* __restrict__ bd, float* __restrict__ Cd)
{
    const int z = blockIdx.z;
    if (z == 1 && blockIdx.y >= (NB * S_DEC) / GBM) return;

    const float* __restrict__ X    = z ? Xd : Xe;
    const float* __restrict__ W    = z ? Wd : We;
    const float* __restrict__ bias = z ? bd : be;
    float* __restrict__ C          = z ? Cd : Ce;

    __shared__ float As[GBK][GBM];
    __shared__ float Bs[GBK][GBN];

    const int tid = threadIdx.x;
    const int tx = tid & 15;
    const int ty = tid >> 4;
    const int row0 = blockIdx.y * GBM;
    const int col0 = blockIdx.x * GBN;

    const int arow = tid >> 2;
    const int acol = (tid & 3) * 4;
    const int brow = tid >> 4;
    const int bcol = (tid & 15) * 4;

    float acc[4][4] = {};

    float4 ra = *(const float4*)&X[(row0 + arow) * DIM + acol];
    float4 rb = *(const float4*)&W[brow * DIM + col0 + bcol];

    for (int k0 = 0; k0 < DIM; k0 += GBK) {
        As[acol + 0][arow] = ra.x;
        As[acol + 1][arow] = ra.y;
        As[acol + 2][arow] = ra.z;
        As[acol + 3][arow] = ra.w;
        *(float4*)&Bs[brow][bcol] = rb;
        __syncthreads();

        if (k0 + GBK < DIM) {
            ra = *(const float4*)&X[(row0 + arow) * DIM + k0 + GBK + acol];
            rb = *(const float4*)&W[(k0 + GBK + brow) * DIM + col0 + bcol];
        }

        #pragma unroll
        for (int k = 0; k < GBK; k++) {
            float4 av = *(const float4*)&As[k][ty * 4];
            float4 bv = *(const float4*)&Bs[k][tx * 4];
            float ar[4] = {av.x, av.y, av.z, av.w};
            float br[4] = {bv.x, bv.y, bv.z, bv.w};
            #pragma unroll
            for (int i = 0; i < 4; i++)
                #pragma unroll
                for (int j = 0; j < 4; j++)
                    acc[i][j] = fmaf(ar[i], br[j], acc[i][j]);
        }
        __syncthreads();
    }

    #pragma unroll
    for (int i = 0; i < 4; i++) {
        const int r = row0 + ty * 4 + i;
        #pragma unroll
        for (int j = 0; j < 4; j++) {
            const int c = col0 + tx * 4 + j;
            C[r * DIM + c] = acc[i][j] + bias[c];
        }
    }
}

// ---------------------------------------------------------------------------
// Attention kernel.
// Block = (batch b, tile of QT=8 q's), 512 threads = 16 warps.
// Warp w -> (q = w>>1, u-half h = w&1). dd/ws slices in registers.
// Each lane accumulates partial scores for a batch of EB=32 encoder rows
// (acc[32]); reduced across the warp with a multi-value butterfly
// (31 shuffles per 32 e's). Two warps' half-sums combined via SMEM.
// ---------------------------------------------------------------------------
#define QT   8
#define EB   32                  // encoder rows per chunk
#define NCH  (S_ENC / EB)        // 8
#define ATH  512
#define CHV  (EB * DIM / 4)      // 4096 float4 per chunk
#define PFT  (CHV / ATH)         // 8 float4 per thread

__device__ __forceinline__ float tanh_approx(float x) {
    float y;
    asm("tanh.approx.f32 %0, %1;" : "=f"(y) : "f"(x));
    return y;
}

__global__ __launch_bounds__(ATH) void attn_kernel(
    const float* __restrict__ enc,      // [B, S_ENC, DIM] raw encodings
    const float* __restrict__ wscore,   // [DIM]
    const float* __restrict__ bscore,   // [1]
    float* __restrict__ out)            // [B, S_DEC, DIM]
{
    extern __shared__ float smem[];
    float* s_de   = smem;                         // 2*EB*DIM   (32768 f)
    float* s_part = s_de + 2 * EB * DIM;          // 16*S_ENC   (4096 f)
    float* s_sc   = s_part + 16 * S_ENC;          // QT*S_ENC   (2048 f)
    float* s_t    = s_sc + QT * S_ENC;            // S_ENC*QT   (2048 f)

    const int b    = blockIdx.y;
    const int q0   = blockIdx.x * QT;
    const int tid  = threadIdx.x;
    const int lane = tid & 31;
    const int w    = tid >> 5;
    const int q    = w >> 1;        // local q in [0,8)
    const int h    = w & 1;         // u-half
    const int u0   = h * 256 + lane;

    // ---- loop-invariant registers -----------------------------------------
    float ddr[8], wsr[8];
    {
        const float* ddp = g_ddec + (b * S_DEC + q0 + q) * DIM;
        #pragma unroll
        for (int i = 0; i < 8; i++) {
            ddr[i] = ddp[u0 + 32 * i];
            wsr[i] = wscore[u0 + 32 * i];
        }
    }

    const float4* gsrc = (const float4*)(g_denc + b * S_ENC * DIM);
    float4* sde4 = (float4*)s_de;

    // prefetch chunk 0 -> store, prefetch chunk 1 -> regs
    float4 r[PFT];
    #pragma unroll
    for (int j = 0; j < PFT; j++) r[j] = gsrc[j * ATH + tid];
    #pragma unroll
    for (int j = 0; j < PFT; j++) sde4[j * ATH + tid] = r[j];
    #pragma unroll
    for (int j = 0; j < PFT; j++) r[j] = gsrc[CHV + j * ATH + tid];
    __syncthreads();

    // ---- score chunks ------------------------------------------------------
    for (int ch = 0; ch < NCH; ch++) {
        const float* de = s_de + (ch & 1) * EB * DIM + u0;

        float acc[EB];
        #pragma unroll
        for (int e = 0; e < EB; e++) {
            float s = 0.f;
            #pragma unroll
            for (int i = 0; i < 8; i++) {
                const float x = ddr[i] + de[e * DIM + 32 * i];
                s = fmaf(tanh_approx(x), wsr[i], s);
            }
            acc[e] = s;
        }

        // multi-value butterfly: after 5 stages lane l holds sum for e=base+l
        #pragma unroll
        for (int s = 16, n = 16; s >= 1; s >>= 1, n >>= 1) {
            const bool hi = (lane & s) != 0;
            #pragma unroll
            for (int j = 0; j < n; j++) {
                const float send = hi ? acc[j] : acc[j + n];
                const float keep = hi ? acc[j + n] : acc[j];
                acc[j] = keep + __shfl_xor_sync(0xFFFFFFFFu, send, s);
            }
        }
        s_part[w * S_ENC + ch * EB + lane] = acc[0];

        __syncthreads();   // buf[(ch+1)&1] free (consumed at chunk ch-1)
        if (ch + 1 < NCH) {
            float4* dbuf = sde4 + ((ch + 1) & 1) * CHV;
            #pragma unroll
            for (int j = 0; j < PFT; j++) dbuf[j * ATH + tid] = r[j];
            if (ch + 2 < NCH) {
                #pragma unroll
                for (int j = 0; j < PFT; j++)
                    r[j] = gsrc[(ch + 2) * CHV + j * ATH + tid];
            }
            __syncthreads();
        }
    }
    __syncthreads();   // all s_part written

    // ---- combine half-sums + bias -----------------------------------------
    const float bsc = bscore[0];
    for (int idx = tid; idx < QT * S_ENC; idx += ATH) {
        const int qq = idx >> 8, e = idx & (S_ENC - 1);
        s_sc[qq * S_ENC + e] =
            s_part[(2 * qq) * S_ENC + e] + s_part[(2 * qq + 1) * S_ENC + e] + bsc;
    }
    __syncthreads();

    // ---- softmax (warps 0-7 handle q=w); write transposed [e][q] ----------
    if (w < QT) {
        float v[S_ENC / 32];
        float m = -1e30f;
        #pragma unroll
        for (int i = 0; i < S_ENC / 32; i++) {
            v[i] = s_sc[w * S_ENC + lane + 32 * i];
            m = fmaxf(m, v[i]);
        }
        #pragma unroll
        for (int off = 16; off; off >>= 1)
            m = fmaxf(m, __shfl_xor_sync(0xFFFFFFFFu, m, off));
        float sum = 0.f;
        #pragma unroll
        for (int i = 0; i < S_ENC / 32; i++) {
            v[i] = __expf(v[i] - m);
            sum += v[i];
        }
        #pragma unroll
        for (int off = 16; off; off >>= 1)
            sum += __shfl_xor_sync(0xFFFFFFFFu, sum, off);
        const float inv = 1.f / sum;
        #pragma unroll
        for (int i = 0; i < S_ENC / 32; i++)
            s_t[(lane + 32 * i) * QT + w] = v[i] * inv;
    }
    __syncthreads();

    // ---- context: warp w owns dims [w*32, w*32+32) across ALL q -----------
    const int d0 = w * 32 + lane;
    float c[QT] = {};
    const float* ep = enc + b * S_ENC * DIM;

    #pragma unroll 4
    for (int e = 0; e < S_ENC; e++) {
        const float ev = ep[e * DIM + d0];
        const float4 w0 = *(const float4*)&s_t[e * QT];       // broadcast
        const float4 w1 = *(const float4*)&s_t[e * QT + 4];
        c[0] = fmaf(w0.x, ev, c[0]);
        c[1] = fmaf(w0.y, ev, c[1]);
        c[2] = fmaf(w0.z, ev, c[2]);
        c[3] = fmaf(w0.w, ev, c[3]);
        c[4] = fmaf(w1.x, ev, c[4]);
        c[5] = fmaf(w1.y, ev, c[5]);
        c[6] = fmaf(w1.z, ev, c[6]);
        c[7] = fmaf(w1.w, ev, c[7]);
    }

    #pragma unroll
    for (int qq = 0; qq < QT; qq++)
        out[(b * S_DEC + q0 + qq) * DIM + d0] = c[qq];
}

#define ATTN_SMEM ((2 * EB * DIM + 16 * S_ENC + 2 * QT * S_ENC) * (int)sizeof(float))

// ---------------------------------------------------------------------------
extern "C" void kernel_launch(void* const* d_in, const int* in_sizes, int n_in,
                              void* d_out, int out_size)
{
    const float* encodings = (const float*)d_in[0];   // [8,256,512]
    const float* decodings = (const float*)d_in[1];   // [8,128,512]
    const float* W_enc     = (const float*)d_in[2];   // [512,512]
    const float* W_dec     = (const float*)d_in[3];   // [512,512]
    const float* W_score   = (const float*)d_in[4];   // [512,1]
    const float* bias_enc  = (const float*)d_in[5];   // [512]
    const float* bias_dec  = (const float*)d_in[6];   // [512]
    const float* bias_sc   = (const float*)d_in[7];   // [1]
    float* out = (float*)d_out;                       // [8,128,512]

    void* p_denc = nullptr;
    void* p_ddec = nullptr;
    cudaGetSymbolAddress(&p_denc, g_denc);
    cudaGetSymbolAddress(&p_ddec, g_ddec);

    cudaFuncSetAttribute(attn_kernel,
                         cudaFuncAttributeMaxDynamicSharedMemorySize, ATTN_SMEM);

    // both projections in one launch (z dimension selects)
    {
        dim3 grid(DIM / GBN, (NB * S_ENC) / GBM, 2);   // (8, 32, 2)
        gemm_bias_kernel<<<grid, 256>>>(encodings, W_enc, bias_enc, (float*)p_denc,
                                        decodings, W_dec, bias_dec, (float*)p_ddec);
    }

    // scores + softmax + context
    {
        dim3 grid(S_DEC / QT, NB);                     // (16, 8)
        attn_kernel<<<grid, ATH, ATTN_SMEM>>>(encodings, W_score, bias_sc, out);
    }
}